// round 1
// baseline (speedup 1.0000x reference)
#include <cuda_runtime.h>
#include <math.h>

#define TT 2048
#define HIDDEN 4096
#define NH 32
#define NKV 8
#define HD 128
#define QDIM (NH*HD)    // 4096
#define KVDIM (NKV*HD)  // 1024

// Scratch (allocation-free rule: __device__ globals)
__device__ float g_q[TT*QDIM];
__device__ float g_k[TT*KVDIM];
__device__ float g_v[TT*KVDIM];
__device__ float g_attn[TT*QDIM];

// ---------------------------------------------------------------------------
// SGEMM: C[M,N] = A[M,K] @ B[K,N], all row-major, fp32.
// 128x128 block, BK=16, 256 threads, 8x8 per thread.
// Requires M%128==0, N%128==0, K%16==0 (true for all our shapes).
// ---------------------------------------------------------------------------
__global__ __launch_bounds__(256, 2)
void sgemm_kernel(const float* __restrict__ A, const float* __restrict__ B,
                  float* __restrict__ C, int M, int N, int K)
{
    const int BM = 128, BN = 128, BK = 16;
    __shared__ float As[BK][BM];   // transposed A tile
    __shared__ float Bs[BK][BN];

    int bm = blockIdx.y * BM;
    int bn = blockIdx.x * BN;
    int tid = threadIdx.x;
    int tx = tid & 15;       // 0..15 -> column group
    int ty = tid >> 4;       // 0..15 -> row group

    float acc[8][8];
#pragma unroll
    for (int i = 0; i < 8; i++)
#pragma unroll
        for (int j = 0; j < 8; j++) acc[i][j] = 0.f;

    for (int k0 = 0; k0 < K; k0 += BK) {
        // Load A tile: 128 rows x 16 cols = 512 float4, 2 per thread
#pragma unroll
        for (int it = 0; it < 2; it++) {
            int e = tid + it * 256;
            int r = e >> 2;
            int c4 = (e & 3) * 4;
            float4 v = *(const float4*)&A[(size_t)(bm + r) * K + k0 + c4];
            As[c4 + 0][r] = v.x;
            As[c4 + 1][r] = v.y;
            As[c4 + 2][r] = v.z;
            As[c4 + 3][r] = v.w;
        }
        // Load B tile: 16 rows x 128 cols = 512 float4, 2 per thread
#pragma unroll
        for (int it = 0; it < 2; it++) {
            int e = tid + it * 256;
            int r = e >> 5;
            int c4 = (e & 31) * 4;
            *(float4*)&Bs[r][c4] = *(const float4*)&B[(size_t)(k0 + r) * N + bn + c4];
        }
        __syncthreads();

#pragma unroll
        for (int k = 0; k < BK; k++) {
            float a[8], b[8];
            *(float4*)&a[0] = *(const float4*)&As[k][ty * 8];
            *(float4*)&a[4] = *(const float4*)&As[k][ty * 8 + 4];
            *(float4*)&b[0] = *(const float4*)&Bs[k][tx * 8];
            *(float4*)&b[4] = *(const float4*)&Bs[k][tx * 8 + 4];
#pragma unroll
            for (int i = 0; i < 8; i++)
#pragma unroll
                for (int j = 0; j < 8; j++)
                    acc[i][j] += a[i] * b[j];
        }
        __syncthreads();
    }

#pragma unroll
    for (int i = 0; i < 8; i++) {
        size_t row = (size_t)(bm + ty * 8 + i) * N + bn + tx * 8;
        *(float4*)&C[row]     = *(float4*)&acc[i][0];
        *(float4*)&C[row + 4] = *(float4*)&acc[i][4];
    }
}

// ---------------------------------------------------------------------------
// Fused RMSNorm + RoPE over q (T*NH rows) and k (T*NKV rows), in place.
// One warp per (t, head) row of 128 elements; lane owns d, d+32, d+64, d+96.
// RoPE pairs: (j, j+64) for j in 0..63.
// ---------------------------------------------------------------------------
__global__ void norm_rope_kernel(float* __restrict__ q, float* __restrict__ k,
                                 const int* __restrict__ positions,
                                 const float* __restrict__ qw,
                                 const float* __restrict__ kw)
{
    const int QROWS = TT * NH;
    const int TOTAL = QROWS + TT * NKV;
    int row = blockIdx.x * (blockDim.x >> 5) + (threadIdx.x >> 5);
    if (row >= TOTAL) return;
    int lane = threadIdx.x & 31;

    float* x;
    const float* w;
    int t;
    if (row < QROWS) {
        t = row / NH;
        x = q + (size_t)row * HD;
        w = qw;
    } else {
        int r2 = row - QROWS;
        t = r2 / NKV;
        x = k + (size_t)r2 * HD;
        w = kw;
    }

    float x0 = x[lane];
    float x1 = x[lane + 32];
    float x2 = x[lane + 64];
    float x3 = x[lane + 96];

    float ss = x0 * x0 + x1 * x1 + x2 * x2 + x3 * x3;
#pragma unroll
    for (int m = 16; m; m >>= 1) ss += __shfl_xor_sync(0xffffffffu, ss, m);

    float rinv = rsqrtf(ss * (1.0f / 128.0f) + 1e-6f);
    x0 *= rinv * w[lane];
    x1 *= rinv * w[lane + 32];
    x2 *= rinv * w[lane + 64];
    x3 *= rinv * w[lane + 96];

    float p = (float)positions[t];
    // pair (lane, lane+64): j = lane ; pair (lane+32, lane+96): j = lane+32
    float invf0 = powf(10000.0f, -(float)lane * (1.0f / 64.0f));
    float invf1 = powf(10000.0f, -(float)(lane + 32) * (1.0f / 64.0f));
    float f0 = p * invf0, f1 = p * invf1;
    float c0 = cosf(f0), s0 = sinf(f0);
    float c1 = cosf(f1), s1 = sinf(f1);

    x[lane]      = x0 * c0 - x2 * s0;
    x[lane + 64] = x2 * c0 + x0 * s0;
    x[lane + 32] = x1 * c1 - x3 * s1;
    x[lane + 96] = x3 * c1 + x1 * s1;
}

// ---------------------------------------------------------------------------
// Causal flash attention. One CTA = (q-tile of 64 rows, head).
// 256 threads: (tx,ty) in 16x16; thread owns S rows 4*ty..+3, S cols 4*tx..+3,
// O rows 4*ty..+3, O cols 8*tx..+7. K and V share one smem buffer.
// ---------------------------------------------------------------------------
#define FBM 64
#define FBN 64
#define KVSTRIDE 132   // HD + 4 pad, keeps float4 alignment, breaks bank conflicts

__global__ __launch_bounds__(256, 2)
void flash_kernel(const float* __restrict__ Q, const float* __restrict__ K,
                  const float* __restrict__ V, float* __restrict__ O)
{
    extern __shared__ float sm[];
    float* Qs  = sm;                   // 64*132
    float* KVs = Qs + FBM * KVSTRIDE;  // 64*132 (K then V)
    float* Ps  = KVs + FBM * KVSTRIDE; // 64*64

    int qt = blockIdx.x;       // q tile index, 0..31
    int h  = blockIdx.y;       // head, 0..31
    int kvh = h / (NH / NKV);
    int tid = threadIdx.x;
    int tx = tid & 15;
    int ty = tid >> 4;

    // Load Q tile: 64 x 128 floats = 2048 float4, 8 per thread
#pragma unroll
    for (int it = 0; it < 8; it++) {
        int e = tid + it * 256;
        int r = e >> 5;
        int c4 = (e & 31) * 4;
        *(float4*)&Qs[r * KVSTRIDE + c4] =
            *(const float4*)&Q[(size_t)(qt * FBM + r) * QDIM + h * HD + c4];
    }

    float m_i[4], l_i[4], o[4][8];
#pragma unroll
    for (int r = 0; r < 4; r++) {
        m_i[r] = -1e30f;
        l_i[r] = 0.f;
#pragma unroll
        for (int c = 0; c < 8; c++) o[r][c] = 0.f;
    }
    const float scale = 0.08838834764831845f;  // 1/sqrt(128)

    for (int j = 0; j <= qt; j++) {
        __syncthreads();  // prior PV reads of KVs/Ps done; Q load done (j==0)
        // Load K tile j
#pragma unroll
        for (int it = 0; it < 8; it++) {
            int e = tid + it * 256;
            int r = e >> 5;
            int c4 = (e & 31) * 4;
            *(float4*)&KVs[r * KVSTRIDE + c4] =
                *(const float4*)&K[(size_t)(j * FBM + r) * KVDIM + kvh * HD + c4];
        }
        __syncthreads();

        // S = Q K^T  (4x4 per thread over d=128)
        float s[4][4];
#pragma unroll
        for (int r = 0; r < 4; r++)
#pragma unroll
            for (int c = 0; c < 4; c++) s[r][c] = 0.f;

        for (int d = 0; d < HD; d += 4) {
            float4 qv[4], kv[4];
#pragma unroll
            for (int r = 0; r < 4; r++)
                qv[r] = *(const float4*)&Qs[(ty * 4 + r) * KVSTRIDE + d];
#pragma unroll
            for (int c = 0; c < 4; c++)
                kv[c] = *(const float4*)&KVs[(tx * 4 + c) * KVSTRIDE + d];
#pragma unroll
            for (int r = 0; r < 4; r++)
#pragma unroll
                for (int c = 0; c < 4; c++)
                    s[r][c] += qv[r].x * kv[c].x + qv[r].y * kv[c].y +
                               qv[r].z * kv[c].z + qv[r].w * kv[c].w;
        }

        bool diag = (j == qt);
#pragma unroll
        for (int r = 0; r < 4; r++) {
            int qr = ty * 4 + r;
            float rowmax = -1e30f;
#pragma unroll
            for (int c = 0; c < 4; c++) {
                s[r][c] *= scale;
                if (diag && (tx * 4 + c) > qr) s[r][c] = -1e30f;
                rowmax = fmaxf(rowmax, s[r][c]);
            }
#pragma unroll
            for (int m = 8; m; m >>= 1)
                rowmax = fmaxf(rowmax, __shfl_xor_sync(0xffffffffu, rowmax, m, 16));
            float mnew = fmaxf(m_i[r], rowmax);
            float fac = __expf(m_i[r] - mnew);
            float psum = 0.f;
#pragma unroll
            for (int c = 0; c < 4; c++) {
                float pv = __expf(s[r][c] - mnew);
                Ps[qr * 64 + tx * 4 + c] = pv;
                psum += pv;
            }
#pragma unroll
            for (int m = 8; m; m >>= 1)
                psum += __shfl_xor_sync(0xffffffffu, psum, m, 16);
            l_i[r] = l_i[r] * fac + psum;
            m_i[r] = mnew;
#pragma unroll
            for (int c = 0; c < 8; c++) o[r][c] *= fac;
        }
        __syncthreads();  // Ps written; all K reads done

        // Load V tile j over the K buffer
#pragma unroll
        for (int it = 0; it < 8; it++) {
            int e = tid + it * 256;
            int r = e >> 5;
            int c4 = (e & 31) * 4;
            *(float4*)&KVs[r * KVSTRIDE + c4] =
                *(const float4*)&V[(size_t)(j * FBM + r) * KVDIM + kvh * HD + c4];
        }
        __syncthreads();

        // O += P @ V
        for (int kk = 0; kk < FBN; kk++) {
            float pv[4];
#pragma unroll
            for (int r = 0; r < 4; r++) pv[r] = Ps[(ty * 4 + r) * 64 + kk];
            float4 v0 = *(const float4*)&KVs[kk * KVSTRIDE + tx * 8];
            float4 v1 = *(const float4*)&KVs[kk * KVSTRIDE + tx * 8 + 4];
#pragma unroll
            for (int r = 0; r < 4; r++) {
                o[r][0] += pv[r] * v0.x;
                o[r][1] += pv[r] * v0.y;
                o[r][2] += pv[r] * v0.z;
                o[r][3] += pv[r] * v0.w;
                o[r][4] += pv[r] * v1.x;
                o[r][5] += pv[r] * v1.y;
                o[r][6] += pv[r] * v1.z;
                o[r][7] += pv[r] * v1.w;
            }
        }
    }

    // Write normalized output
#pragma unroll
    for (int r = 0; r < 4; r++) {
        float inv = 1.0f / l_i[r];
        size_t row = (size_t)(qt * FBM + ty * 4 + r) * QDIM + h * HD + tx * 8;
        float4 a, b;
        a.x = o[r][0] * inv; a.y = o[r][1] * inv;
        a.z = o[r][2] * inv; a.w = o[r][3] * inv;
        b.x = o[r][4] * inv; b.y = o[r][5] * inv;
        b.z = o[r][6] * inv; b.w = o[r][7] * inv;
        *(float4*)&O[row]     = a;
        *(float4*)&O[row + 4] = b;
    }
}

// ---------------------------------------------------------------------------
// Launch
// ---------------------------------------------------------------------------
extern "C" void kernel_launch(void* const* d_in, const int* in_sizes, int n_in,
                              void* d_out, int out_size)
{
    const int*   positions = (const int*)d_in[0];
    const float* hidden    = (const float*)d_in[1];
    const float* wq        = (const float*)d_in[2];
    const float* wk        = (const float*)d_in[3];
    const float* wv        = (const float*)d_in[4];
    const float* wo        = (const float*)d_in[5];
    const float* qnw       = (const float*)d_in[6];
    const float* knw       = (const float*)d_in[7];
    float* out = (float*)d_out;

    float *q, *k, *v, *attn;
    cudaGetSymbolAddress((void**)&q, g_q);
    cudaGetSymbolAddress((void**)&k, g_k);
    cudaGetSymbolAddress((void**)&v, g_v);
    cudaGetSymbolAddress((void**)&attn, g_attn);

    // QKV projections
    {
        dim3 gq(QDIM / 128, TT / 128);
        sgemm_kernel<<<gq, 256>>>(hidden, wq, q, TT, QDIM, HIDDEN);
        dim3 gk(KVDIM / 128, TT / 128);
        sgemm_kernel<<<gk, 256>>>(hidden, wk, k, TT, KVDIM, HIDDEN);
        sgemm_kernel<<<gk, 256>>>(hidden, wv, v, TT, KVDIM, HIDDEN);
    }

    // RMSNorm + RoPE (q and k)
    {
        int rows = TT * NH + TT * NKV;
        int rows_per_block = 4;  // 128 threads
        int blocks = (rows + rows_per_block - 1) / rows_per_block;
        norm_rope_kernel<<<blocks, 128>>>(q, k, positions, qnw, knw);
    }

    // Flash attention
    {
        int smem = (2 * FBM * KVSTRIDE + FBM * FBN) * (int)sizeof(float); // 83968
        cudaFuncSetAttribute(flash_kernel,
                             cudaFuncAttributeMaxDynamicSharedMemorySize, smem);
        dim3 g(TT / FBM, NH);
        flash_kernel<<<g, 256, smem>>>(q, k, v, attn);
    }

    // Output projection
    {
        dim3 go(HIDDEN / 128, TT / 128);
        sgemm_kernel<<<go, 256>>>(attn, wo, out, TT, HIDDEN, HIDDEN);
    }
}

// round 4
// speedup vs baseline: 3.5280x; 3.5280x over previous
#include <cuda_runtime.h>
#include <math.h>
#include <stdint.h>

#define TT 2048
#define HIDDEN 4096
#define NH 32
#define NKV 8
#define HD 128
#define QDIM (NH*HD)    // 4096
#define KVDIM (NKV*HD)  // 1024

// Scratch (allocation-free rule: __device__ globals)
__device__ float g_q[TT*QDIM];
__device__ float g_k[TT*KVDIM];
__device__ float g_v[TT*KVDIM];
__device__ float g_attn[TT*QDIM];

// ---------------------------------------------------------------------------
// Helpers: tf32 convert, mma, cp.async
// ---------------------------------------------------------------------------
__device__ __forceinline__ uint32_t f2tf(float x) {
    uint32_t r;
    asm("cvt.rna.tf32.f32 %0, %1;" : "=r"(r) : "f"(x));
    return r;
}

__device__ __forceinline__ void mma_tf32(float* c, const uint32_t* a, const uint32_t* b) {
    asm volatile(
        "mma.sync.aligned.m16n8k8.row.col.f32.tf32.tf32.f32 "
        "{%0,%1,%2,%3}, {%4,%5,%6,%7}, {%8,%9}, {%0,%1,%2,%3};"
        : "+f"(c[0]), "+f"(c[1]), "+f"(c[2]), "+f"(c[3])
        : "r"(a[0]), "r"(a[1]), "r"(a[2]), "r"(a[3]), "r"(b[0]), "r"(b[1]));
}

__device__ __forceinline__ void cp16(void* smem_dst, const void* gsrc) {
    uint32_t d = (uint32_t)__cvta_generic_to_shared(smem_dst);
    asm volatile("cp.async.cg.shared.global [%0], [%1], 16;" :: "r"(d), "l"(gsrc));
}
__device__ __forceinline__ void cp_commit() { asm volatile("cp.async.commit_group;"); }
template<int N> __device__ __forceinline__ void cp_wait() {
    asm volatile("cp.async.wait_group %0;" :: "n"(N));
}

// ---------------------------------------------------------------------------
// TF32 tensor-core GEMM: C[M,N] = A[M,K] @ B[K,N], row-major fp32 in/out.
// 128x128 CTA tile, BK=16, 256 threads (8 warps as 4x2, warp tile 32x64).
// Double-buffered cp.async. Requires M%128==0, N%128==0, K%16==0.
// ---------------------------------------------------------------------------
__global__ __launch_bounds__(256)
void tf32_gemm(const float* __restrict__ A, const float* __restrict__ B,
               float* __restrict__ C, int M, int N, int K)
{
    __shared__ float As[2][128][20];
    __shared__ float Bs[2][16][136];

    int bm = blockIdx.y * 128, bn = blockIdx.x * 128;
    int tid = threadIdx.x;
    int w = tid >> 5, lane = tid & 31, g = lane >> 2, tg = lane & 3;
    int wm = (w >> 1) * 32, wn = (w & 1) * 64;

    float acc[2][8][4];
#pragma unroll
    for (int mt = 0; mt < 2; mt++)
#pragma unroll
        for (int nt = 0; nt < 8; nt++)
#pragma unroll
            for (int i = 0; i < 4; i++) acc[mt][nt][i] = 0.f;

    int ar = tid >> 2, ac = (tid & 3) * 4;   // A loader coords
    int br = tid >> 5, bc = (tid & 31) * 4;  // B loader coords

    int ntile = K / 16;
    // prefetch tile 0
    cp16(&As[0][ar][ac],      &A[(size_t)(bm + ar) * K + ac]);
    cp16(&As[0][64 + ar][ac], &A[(size_t)(bm + 64 + ar) * K + ac]);
    cp16(&Bs[0][br][bc],      &B[(size_t)(br) * N + bn + bc]);
    cp16(&Bs[0][8 + br][bc],  &B[(size_t)(8 + br) * N + bn + bc]);
    cp_commit();

    for (int t = 0; t < ntile; t++) {
        if (t + 1 < ntile) {
            int s = (t + 1) & 1, k0 = (t + 1) * 16;
            cp16(&As[s][ar][ac],      &A[(size_t)(bm + ar) * K + k0 + ac]);
            cp16(&As[s][64 + ar][ac], &A[(size_t)(bm + 64 + ar) * K + k0 + ac]);
            cp16(&Bs[s][br][bc],      &B[(size_t)(k0 + br) * N + bn + bc]);
            cp16(&Bs[s][8 + br][bc],  &B[(size_t)(k0 + 8 + br) * N + bn + bc]);
            cp_commit();
            cp_wait<1>();
        } else {
            cp_wait<0>();
        }
        __syncthreads();

        const float (*as)[20]  = As[t & 1];
        const float (*bs)[136] = Bs[t & 1];
#pragma unroll
        for (int kk = 0; kk < 16; kk += 8) {
            uint32_t af[2][4];
#pragma unroll
            for (int mt = 0; mt < 2; mt++) {
                int m = wm + mt * 16 + g;
                af[mt][0] = f2tf(as[m][kk + tg]);
                af[mt][1] = f2tf(as[m + 8][kk + tg]);
                af[mt][2] = f2tf(as[m][kk + tg + 4]);
                af[mt][3] = f2tf(as[m + 8][kk + tg + 4]);
            }
            uint32_t bf[8][2];
#pragma unroll
            for (int nt = 0; nt < 8; nt++) {
                int n = wn + nt * 8 + g;
                bf[nt][0] = f2tf(bs[kk + tg][n]);
                bf[nt][1] = f2tf(bs[kk + tg + 4][n]);
            }
#pragma unroll
            for (int mt = 0; mt < 2; mt++)
#pragma unroll
                for (int nt = 0; nt < 8; nt++)
                    mma_tf32(acc[mt][nt], af[mt], bf[nt]);
        }
        __syncthreads();
    }

#pragma unroll
    for (int mt = 0; mt < 2; mt++)
#pragma unroll
        for (int nt = 0; nt < 8; nt++) {
            size_t r0 = (size_t)(bm + wm + mt * 16 + g) * N + bn + wn + nt * 8 + 2 * tg;
            size_t r1 = r0 + (size_t)8 * N;
            *(float2*)&C[r0] = make_float2(acc[mt][nt][0], acc[mt][nt][1]);
            *(float2*)&C[r1] = make_float2(acc[mt][nt][2], acc[mt][nt][3]);
        }
}

// ---------------------------------------------------------------------------
// Fused RMSNorm + RoPE
// ---------------------------------------------------------------------------
__global__ void norm_rope_kernel(float* __restrict__ q, float* __restrict__ k,
                                 const int* __restrict__ positions,
                                 const float* __restrict__ qw,
                                 const float* __restrict__ kw)
{
    const int QROWS = TT * NH;
    const int TOTAL = QROWS + TT * NKV;
    int row = blockIdx.x * (blockDim.x >> 5) + (threadIdx.x >> 5);
    if (row >= TOTAL) return;
    int lane = threadIdx.x & 31;

    float* x;
    const float* w;
    int t;
    if (row < QROWS) {
        t = row / NH;
        x = q + (size_t)row * HD;
        w = qw;
    } else {
        int r2 = row - QROWS;
        t = r2 / NKV;
        x = k + (size_t)r2 * HD;
        w = kw;
    }

    float x0 = x[lane], x1 = x[lane + 32], x2 = x[lane + 64], x3 = x[lane + 96];

    float ss = x0 * x0 + x1 * x1 + x2 * x2 + x3 * x3;
#pragma unroll
    for (int m = 16; m; m >>= 1) ss += __shfl_xor_sync(0xffffffffu, ss, m);

    float rinv = rsqrtf(ss * (1.0f / 128.0f) + 1e-6f);
    x0 *= rinv * w[lane];
    x1 *= rinv * w[lane + 32];
    x2 *= rinv * w[lane + 64];
    x3 *= rinv * w[lane + 96];

    float p = (float)positions[t];
    float invf0 = powf(10000.0f, -(float)lane * (1.0f / 64.0f));
    float invf1 = powf(10000.0f, -(float)(lane + 32) * (1.0f / 64.0f));
    float f0 = p * invf0, f1 = p * invf1;
    float c0 = cosf(f0), s0 = sinf(f0);
    float c1 = cosf(f1), s1 = sinf(f1);

    x[lane]      = x0 * c0 - x2 * s0;
    x[lane + 64] = x2 * c0 + x0 * s0;
    x[lane + 32] = x1 * c1 - x3 * s1;
    x[lane + 96] = x3 * c1 + x1 * s1;
}

// ---------------------------------------------------------------------------
// Causal flash attention with tf32 mma for QK^T and PV.
// CTA = (64 q-rows, head). 256 thr / 8 warps: warp (wm=w>>1 -> 16-row band,
// wn=w&1 -> column half). S: 64x64; O: 64x128.
// ---------------------------------------------------------------------------
#define LSTR 132
#define PSTR 68

__global__ __launch_bounds__(256, 2)
void flash_tf32(const float* __restrict__ Q, const float* __restrict__ K,
                const float* __restrict__ V, float* __restrict__ O)
{
    extern __shared__ float sm[];
    float* Qs   = sm;                  // [64][132] tf32 bits
    float* KVs  = Qs + 64 * LSTR;      // [64][132] tf32 bits (K then V)
    float* Ps   = KVs + 64 * LSTR;     // [64][68]  tf32 bits
    float* Smax = Ps + 64 * PSTR;      // [64][2]
    float* Ssum = Smax + 128;          // [64][2]

    int qt = blockIdx.x;
    int h  = blockIdx.y;
    int kvh = h >> 2;                  // NH/NKV = 4
    int tid = threadIdx.x;
    int w = tid >> 5, lane = tid & 31, g = lane >> 2, tg = lane & 3;
    int wm = (w >> 1) * 16;
    int wn = w & 1;

    // Load Q tile, convert to tf32 bits
#pragma unroll
    for (int it = 0; it < 8; it++) {
        int e = tid + it * 256;
        int r = e >> 5, c4 = (e & 31) * 4;
        float4 v = *(const float4*)&Q[(size_t)(qt * 64 + r) * QDIM + h * HD + c4];
        float4 o4 = make_float4(__uint_as_float(f2tf(v.x)), __uint_as_float(f2tf(v.y)),
                                __uint_as_float(f2tf(v.z)), __uint_as_float(f2tf(v.w)));
        *(float4*)&Qs[r * LSTR + c4] = o4;
    }

    float m0 = -1e30f, m1 = -1e30f, l0 = 0.f, l1 = 0.f;
    float o[8][4];
#pragma unroll
    for (int nt = 0; nt < 8; nt++)
#pragma unroll
        for (int i = 0; i < 4; i++) o[nt][i] = 0.f;

    const float scale = 0.08838834764831845f;
    int row0 = wm + g, row1 = wm + g + 8;

    for (int j = 0; j <= qt; j++) {
        __syncthreads();   // prior iter's PV reads of KVs/Ps done; Q load done (j==0)
        // Load K tile j (tf32)
#pragma unroll
        for (int it = 0; it < 8; it++) {
            int e = tid + it * 256;
            int r = e >> 5, c4 = (e & 31) * 4;
            float4 v = *(const float4*)&K[(size_t)(j * 64 + r) * KVDIM + kvh * HD + c4];
            float4 o4 = make_float4(__uint_as_float(f2tf(v.x)), __uint_as_float(f2tf(v.y)),
                                    __uint_as_float(f2tf(v.z)), __uint_as_float(f2tf(v.w)));
            *(float4*)&KVs[r * LSTR + c4] = o4;
        }
        __syncthreads();

        // S = Q K^T (warp region: rows wm..wm+15, cols wn*32..wn*32+31)
        float sacc[4][4];
#pragma unroll
        for (int nt = 0; nt < 4; nt++)
#pragma unroll
            for (int i = 0; i < 4; i++) sacc[nt][i] = 0.f;

#pragma unroll
        for (int kk = 0; kk < HD; kk += 8) {
            uint32_t a[4];
            a[0] = __float_as_uint(Qs[row0 * LSTR + kk + tg]);
            a[1] = __float_as_uint(Qs[row1 * LSTR + kk + tg]);
            a[2] = __float_as_uint(Qs[row0 * LSTR + kk + tg + 4]);
            a[3] = __float_as_uint(Qs[row1 * LSTR + kk + tg + 4]);
#pragma unroll
            for (int nt = 0; nt < 4; nt++) {
                int n = wn * 32 + nt * 8 + g;
                uint32_t b[2];
                b[0] = __float_as_uint(KVs[n * LSTR + kk + tg]);
                b[1] = __float_as_uint(KVs[n * LSTR + kk + tg + 4]);
                mma_tf32(sacc[nt], a, b);
            }
        }

        // scale, causal mask, partial row max
        bool diag = (j == qt);
        float pm0 = -1e30f, pm1 = -1e30f;
#pragma unroll
        for (int nt = 0; nt < 4; nt++) {
            int cb = wn * 32 + nt * 8 + 2 * tg;
#pragma unroll
            for (int cc = 0; cc < 2; cc++) {
                float s0 = sacc[nt][cc] * scale;
                float s1 = sacc[nt][2 + cc] * scale;
                if (diag && (cb + cc) > row0) s0 = -1e30f;
                if (diag && (cb + cc) > row1) s1 = -1e30f;
                sacc[nt][cc] = s0; sacc[nt][2 + cc] = s1;
                pm0 = fmaxf(pm0, s0); pm1 = fmaxf(pm1, s1);
            }
        }
        pm0 = fmaxf(pm0, __shfl_xor_sync(0xffffffffu, pm0, 1));
        pm0 = fmaxf(pm0, __shfl_xor_sync(0xffffffffu, pm0, 2));
        pm1 = fmaxf(pm1, __shfl_xor_sync(0xffffffffu, pm1, 1));
        pm1 = fmaxf(pm1, __shfl_xor_sync(0xffffffffu, pm1, 2));
        if (tg == 0) { Smax[row0 * 2 + wn] = pm0; Smax[row1 * 2 + wn] = pm1; }
        __syncthreads();

        float mn0 = fmaxf(m0, fmaxf(Smax[row0 * 2], Smax[row0 * 2 + 1]));
        float mn1 = fmaxf(m1, fmaxf(Smax[row1 * 2], Smax[row1 * 2 + 1]));
        float fac0 = __expf(m0 - mn0), fac1 = __expf(m1 - mn1);

        float ps0 = 0.f, ps1 = 0.f;
#pragma unroll
        for (int nt = 0; nt < 4; nt++) {
            float p00 = __expf(sacc[nt][0] - mn0), p01 = __expf(sacc[nt][1] - mn0);
            float p10 = __expf(sacc[nt][2] - mn1), p11 = __expf(sacc[nt][3] - mn1);
            ps0 += p00 + p01; ps1 += p10 + p11;
            int cb = wn * 32 + nt * 8 + 2 * tg;
            *(float2*)&Ps[row0 * PSTR + cb] =
                make_float2(__uint_as_float(f2tf(p00)), __uint_as_float(f2tf(p01)));
            *(float2*)&Ps[row1 * PSTR + cb] =
                make_float2(__uint_as_float(f2tf(p10)), __uint_as_float(f2tf(p11)));
        }
        ps0 += __shfl_xor_sync(0xffffffffu, ps0, 1);
        ps0 += __shfl_xor_sync(0xffffffffu, ps0, 2);
        ps1 += __shfl_xor_sync(0xffffffffu, ps1, 1);
        ps1 += __shfl_xor_sync(0xffffffffu, ps1, 2);
        if (tg == 0) { Ssum[row0 * 2 + wn] = ps0; Ssum[row1 * 2 + wn] = ps1; }

#pragma unroll
        for (int nt = 0; nt < 8; nt++) {
            o[nt][0] *= fac0; o[nt][1] *= fac0;
            o[nt][2] *= fac1; o[nt][3] *= fac1;
        }
        m0 = mn0; m1 = mn1;
        __syncthreads();   // Ps + Ssum visible

        l0 = l0 * fac0 + Ssum[row0 * 2] + Ssum[row0 * 2 + 1];
        l1 = l1 * fac1 + Ssum[row1 * 2] + Ssum[row1 * 2 + 1];

        // Load V tile j over KVs
#pragma unroll
        for (int it = 0; it < 8; it++) {
            int e = tid + it * 256;
            int r = e >> 5, c4 = (e & 31) * 4;
            float4 v = *(const float4*)&V[(size_t)(j * 64 + r) * KVDIM + kvh * HD + c4];
            float4 o4 = make_float4(__uint_as_float(f2tf(v.x)), __uint_as_float(f2tf(v.y)),
                                    __uint_as_float(f2tf(v.z)), __uint_as_float(f2tf(v.w)));
            *(float4*)&KVs[r * LSTR + c4] = o4;
        }
        __syncthreads();

        // O += P @ V. B-frag of "V^T" read straight from KVs[s][d] by index map.
#pragma unroll
        for (int kk = 0; kk < 64; kk += 8) {
            uint32_t a[4];
            a[0] = __float_as_uint(Ps[row0 * PSTR + kk + tg]);
            a[1] = __float_as_uint(Ps[row1 * PSTR + kk + tg]);
            a[2] = __float_as_uint(Ps[row0 * PSTR + kk + tg + 4]);
            a[3] = __float_as_uint(Ps[row1 * PSTR + kk + tg + 4]);
#pragma unroll
            for (int nt = 0; nt < 8; nt++) {
                int n = wn * 64 + nt * 8 + g;
                uint32_t b[2];
                b[0] = __float_as_uint(KVs[(kk + tg) * LSTR + n]);
                b[1] = __float_as_uint(KVs[(kk + tg + 4) * LSTR + n]);
                mma_tf32(o[nt], a, b);
            }
        }
    }

    // Epilogue: normalize + store
    float inv0 = 1.f / l0, inv1 = 1.f / l1;
#pragma unroll
    for (int nt = 0; nt < 8; nt++) {
        int colg = h * HD + wn * 64 + nt * 8 + 2 * tg;
        size_t r0 = (size_t)(qt * 64 + row0) * QDIM + colg;
        size_t r1 = (size_t)(qt * 64 + row1) * QDIM + colg;
        *(float2*)&O[r0] = make_float2(o[nt][0] * inv0, o[nt][1] * inv0);
        *(float2*)&O[r1] = make_float2(o[nt][2] * inv1, o[nt][3] * inv1);
    }
}

// ---------------------------------------------------------------------------
// Launch
// ---------------------------------------------------------------------------
extern "C" void kernel_launch(void* const* d_in, const int* in_sizes, int n_in,
                              void* d_out, int out_size)
{
    const int*   positions = (const int*)d_in[0];
    const float* hidden    = (const float*)d_in[1];
    const float* wq        = (const float*)d_in[2];
    const float* wk        = (const float*)d_in[3];
    const float* wv        = (const float*)d_in[4];
    const float* wo        = (const float*)d_in[5];
    const float* qnw       = (const float*)d_in[6];
    const float* knw       = (const float*)d_in[7];
    float* out = (float*)d_out;

    float *q, *k, *v, *attn;
    cudaGetSymbolAddress((void**)&q, g_q);
    cudaGetSymbolAddress((void**)&k, g_k);
    cudaGetSymbolAddress((void**)&v, g_v);
    cudaGetSymbolAddress((void**)&attn, g_attn);

    // QKV projections (tf32 tensor cores)
    {
        dim3 gq(QDIM / 128, TT / 128);
        tf32_gemm<<<gq, 256>>>(hidden, wq, q, TT, QDIM, HIDDEN);
        dim3 gk(KVDIM / 128, TT / 128);
        tf32_gemm<<<gk, 256>>>(hidden, wk, k, TT, KVDIM, HIDDEN);
        tf32_gemm<<<gk, 256>>>(hidden, wv, v, TT, KVDIM, HIDDEN);
    }

    // RMSNorm + RoPE
    {
        int rows = TT * NH + TT * NKV;
        int blocks = (rows + 3) / 4;
        norm_rope_kernel<<<blocks, 128>>>(q, k, positions, qnw, knw);
    }

    // Flash attention (tf32 tensor cores)
    {
        int smem = (2 * 64 * LSTR + 64 * PSTR + 256) * (int)sizeof(float); // 86016
        cudaFuncSetAttribute(flash_tf32,
                             cudaFuncAttributeMaxDynamicSharedMemorySize, smem);
        dim3 g(TT / 64, NH);
        flash_tf32<<<g, 256, smem>>>(q, k, v, attn);
    }

    // Output projection
    {
        dim3 go(HIDDEN / 128, TT / 128);
        tf32_gemm<<<go, 256>>>(attn, wo, out, TT, HIDDEN, HIDDEN);
    }
}

// round 6
// speedup vs baseline: 3.7765x; 1.0704x over previous
#include <cuda_runtime.h>
#include <math.h>
#include <stdint.h>

#define TT 2048
#define HIDDEN 4096
#define NH 32
#define NKV 8
#define HD 128
#define QDIM (NH*HD)    // 4096
#define KVDIM (NKV*HD)  // 1024

// Scratch (allocation-free rule: __device__ globals)
__device__ float g_q[TT*QDIM];
__device__ float g_k[TT*KVDIM];
__device__ float g_v[TT*KVDIM];
__device__ float g_attn[TT*QDIM];        // tf32-rounded (flash epilogue)
__device__ float g_hid[TT*HIDDEN];       // tf32-rounded hidden
__device__ float g_wqR[HIDDEN*QDIM];     // tf32-rounded weights (layout unchanged)
__device__ float g_wkR[HIDDEN*KVDIM];
__device__ float g_wvR[HIDDEN*KVDIM];
__device__ float g_woR[QDIM*HIDDEN];

// ---------------------------------------------------------------------------
// Helpers
// ---------------------------------------------------------------------------
__device__ __forceinline__ uint32_t f2tf(float x) {
    uint32_t r;
    asm("cvt.rna.tf32.f32 %0, %1;" : "=r"(r) : "f"(x));
    return r;
}

__device__ __forceinline__ void mma_tf32(float* c, const uint32_t* a, const uint32_t* b) {
    asm volatile(
        "mma.sync.aligned.m16n8k8.row.col.f32.tf32.tf32.f32 "
        "{%0,%1,%2,%3}, {%4,%5,%6,%7}, {%8,%9}, {%0,%1,%2,%3};"
        : "+f"(c[0]), "+f"(c[1]), "+f"(c[2]), "+f"(c[3])
        : "r"(a[0]), "r"(a[1]), "r"(a[2]), "r"(a[3]), "r"(b[0]), "r"(b[1]));
}

__device__ __forceinline__ void cp16(void* smem_dst, const void* gsrc) {
    uint32_t d = (uint32_t)__cvta_generic_to_shared(smem_dst);
    asm volatile("cp.async.cg.shared.global [%0], [%1], 16;" :: "r"(d), "l"(gsrc));
}
__device__ __forceinline__ void cp_commit() { asm volatile("cp.async.commit_group;"); }
template<int N> __device__ __forceinline__ void cp_wait() {
    asm volatile("cp.async.wait_group %0;" :: "n"(N));
}

// ---------------------------------------------------------------------------
// Prep: elementwise tf32 rounding (inputs pre-rounded so hot loops skip cvt)
// ---------------------------------------------------------------------------
__global__ void round_tf32(const float* __restrict__ src, float* __restrict__ dst, int n4)
{
    int i = blockIdx.x * blockDim.x + threadIdx.x;
    if (i >= n4) return;
    float4 v = ((const float4*)src)[i];
    ((float4*)dst)[i] = make_float4(
        __uint_as_float(f2tf(v.x)), __uint_as_float(f2tf(v.y)),
        __uint_as_float(f2tf(v.z)), __uint_as_float(f2tf(v.w)));
}

// ---------------------------------------------------------------------------
// TF32 tensor-core GEMM: C[M,N] = A[M,K] @ B[K,N], row-major, inputs already
// tf32-rounded bits. 128x128 CTA tile, BK=32, 256 threads (8 warps, 4x2,
// warp tile 32x64), double-buffered cp.async, sync every 4 k-steps.
// ---------------------------------------------------------------------------
#define GAS 36    // As k-stride: (36m+k)%32=(4m+k)%32 -> frag reads conflict-free
#define GBS 136   // Bs n-stride: (136k+n)%32=(8k+n)%32 -> frag reads conflict-free
#define GSMEM_FLOATS (2*128*GAS + 2*32*GBS)

__global__ __launch_bounds__(256, 2)
void tf32_gemm(const float* __restrict__ A, const float* __restrict__ B,
               float* __restrict__ C, int M, int N, int K)
{
    extern __shared__ float smem[];
    float (*As)[128][GAS] = (float(*)[128][GAS])smem;            // [2][128][36]
    float (*Bs)[32][GBS]  = (float(*)[32][GBS])(smem + 2*128*GAS); // [2][32][136]

    int bm = blockIdx.y * 128, bn = blockIdx.x * 128;
    int tid = threadIdx.x;
    int w = tid >> 5, lane = tid & 31, g = lane >> 2, tg = lane & 3;
    int wm = (w >> 1) * 32, wn = (w & 1) * 64;

    float acc[2][8][4];
#pragma unroll
    for (int mt = 0; mt < 2; mt++)
#pragma unroll
        for (int nt = 0; nt < 8; nt++)
#pragma unroll
            for (int i = 0; i < 4; i++) acc[mt][nt][i] = 0.f;

    // Loader coords: A tile 128x32 = 1024 float4 (4/thread); B tile 32x128 same.
    int ntile = K / 32;

    auto issue = [&](int t) {
        int s = t & 1;
        size_t k0 = (size_t)t * 32;
#pragma unroll
        for (int i = 0; i < 4; i++) {
            int e = tid + i * 256;
            int ar = e >> 3, ac = (e & 7) * 4;
            cp16(&As[s][ar][ac], &A[(size_t)(bm + ar) * K + k0 + ac]);
            int br = e >> 5, bc = (e & 31) * 4;
            cp16(&Bs[s][br][bc], &B[(size_t)(k0 + br) * N + bn + bc]);
        }
        cp_commit();
    };

    issue(0);

    for (int t = 0; t < ntile; t++) {
        if (t + 1 < ntile) { issue(t + 1); cp_wait<1>(); }
        else               { cp_wait<0>(); }
        __syncthreads();

        const float (*as)[GAS] = As[t & 1];
        const float (*bs)[GBS] = Bs[t & 1];
#pragma unroll
        for (int kk = 0; kk < 32; kk += 8) {
            uint32_t af[2][4];
#pragma unroll
            for (int mt = 0; mt < 2; mt++) {
                int m = wm + mt * 16 + g;
                af[mt][0] = __float_as_uint(as[m][kk + tg]);
                af[mt][1] = __float_as_uint(as[m + 8][kk + tg]);
                af[mt][2] = __float_as_uint(as[m][kk + tg + 4]);
                af[mt][3] = __float_as_uint(as[m + 8][kk + tg + 4]);
            }
            uint32_t bf[8][2];
#pragma unroll
            for (int nt = 0; nt < 8; nt++) {
                int n = wn + nt * 8 + g;
                bf[nt][0] = __float_as_uint(bs[kk + tg][n]);
                bf[nt][1] = __float_as_uint(bs[kk + tg + 4][n]);
            }
#pragma unroll
            for (int mt = 0; mt < 2; mt++)
#pragma unroll
                for (int nt = 0; nt < 8; nt++)
                    mma_tf32(acc[mt][nt], af[mt], bf[nt]);
        }
        __syncthreads();
    }

#pragma unroll
    for (int mt = 0; mt < 2; mt++)
#pragma unroll
        for (int nt = 0; nt < 8; nt++) {
            size_t r0 = (size_t)(bm + wm + mt * 16 + g) * N + bn + wn + nt * 8 + 2 * tg;
            size_t r1 = r0 + (size_t)8 * N;
            *(float2*)&C[r0] = make_float2(acc[mt][nt][0], acc[mt][nt][1]);
            *(float2*)&C[r1] = make_float2(acc[mt][nt][2], acc[mt][nt][3]);
        }
}

// ---------------------------------------------------------------------------
// Fused RMSNorm + RoPE; outputs tf32-rounded bits (flash reads them raw)
// ---------------------------------------------------------------------------
__global__ void norm_rope_kernel(float* __restrict__ q, float* __restrict__ k,
                                 const int* __restrict__ positions,
                                 const float* __restrict__ qw,
                                 const float* __restrict__ kw)
{
    const int QROWS = TT * NH;
    const int TOTAL = QROWS + TT * NKV;
    int row = blockIdx.x * (blockDim.x >> 5) + (threadIdx.x >> 5);
    if (row >= TOTAL) return;
    int lane = threadIdx.x & 31;

    float* x;
    const float* w;
    int t;
    if (row < QROWS) {
        t = row / NH;
        x = q + (size_t)row * HD;
        w = qw;
    } else {
        int r2 = row - QROWS;
        t = r2 / NKV;
        x = k + (size_t)r2 * HD;
        w = kw;
    }

    float x0 = x[lane], x1 = x[lane + 32], x2 = x[lane + 64], x3 = x[lane + 96];

    float ss = x0 * x0 + x1 * x1 + x2 * x2 + x3 * x3;
#pragma unroll
    for (int m = 16; m; m >>= 1) ss += __shfl_xor_sync(0xffffffffu, ss, m);

    float rinv = rsqrtf(ss * (1.0f / 128.0f) + 1e-6f);
    x0 *= rinv * w[lane];
    x1 *= rinv * w[lane + 32];
    x2 *= rinv * w[lane + 64];
    x3 *= rinv * w[lane + 96];

    float p = (float)positions[t];
    float invf0 = powf(10000.0f, -(float)lane * (1.0f / 64.0f));
    float invf1 = powf(10000.0f, -(float)(lane + 32) * (1.0f / 64.0f));
    float f0 = p * invf0, f1 = p * invf1;
    float c0 = cosf(f0), s0 = sinf(f0);
    float c1 = cosf(f1), s1 = sinf(f1);

    x[lane]      = __uint_as_float(f2tf(x0 * c0 - x2 * s0));
    x[lane + 64] = __uint_as_float(f2tf(x2 * c0 + x0 * s0));
    x[lane + 32] = __uint_as_float(f2tf(x1 * c1 - x3 * s1));
    x[lane + 96] = __uint_as_float(f2tf(x3 * c1 + x1 * s1));
}

// ---------------------------------------------------------------------------
// Causal flash attention, tf32 mma; Q/K/V arrive pre-rounded (pure copies in)
// ---------------------------------------------------------------------------
#define LSTR 132
#define PSTR 68

__global__ __launch_bounds__(256, 2)
void flash_tf32(const float* __restrict__ Q, const float* __restrict__ K,
                const float* __restrict__ V, float* __restrict__ O)
{
    extern __shared__ float sm[];
    float* Qs   = sm;
    float* KVs  = Qs + 64 * LSTR;
    float* Ps   = KVs + 64 * LSTR;
    float* Smax = Ps + 64 * PSTR;
    float* Ssum = Smax + 128;

    int qt = blockIdx.x;
    int h  = blockIdx.y;
    int kvh = h >> 2;
    int tid = threadIdx.x;
    int w = tid >> 5, lane = tid & 31, g = lane >> 2, tg = lane & 3;
    int wm = (w >> 1) * 16;
    int wn = w & 1;

#pragma unroll
    for (int it = 0; it < 8; it++) {
        int e = tid + it * 256;
        int r = e >> 5, c4 = (e & 31) * 4;
        *(float4*)&Qs[r * LSTR + c4] =
            *(const float4*)&Q[(size_t)(qt * 64 + r) * QDIM + h * HD + c4];
    }

    float m0 = -1e30f, m1 = -1e30f, l0 = 0.f, l1 = 0.f;
    float o[8][4];
#pragma unroll
    for (int nt = 0; nt < 8; nt++)
#pragma unroll
        for (int i = 0; i < 4; i++) o[nt][i] = 0.f;

    const float scale = 0.08838834764831845f;
    int row0 = wm + g, row1 = wm + g + 8;

    for (int j = 0; j <= qt; j++) {
        __syncthreads();
#pragma unroll
        for (int it = 0; it < 8; it++) {
            int e = tid + it * 256;
            int r = e >> 5, c4 = (e & 31) * 4;
            *(float4*)&KVs[r * LSTR + c4] =
                *(const float4*)&K[(size_t)(j * 64 + r) * KVDIM + kvh * HD + c4];
        }
        __syncthreads();

        float sacc[4][4];
#pragma unroll
        for (int nt = 0; nt < 4; nt++)
#pragma unroll
            for (int i = 0; i < 4; i++) sacc[nt][i] = 0.f;

#pragma unroll
        for (int kk = 0; kk < HD; kk += 8) {
            uint32_t a[4];
            a[0] = __float_as_uint(Qs[row0 * LSTR + kk + tg]);
            a[1] = __float_as_uint(Qs[row1 * LSTR + kk + tg]);
            a[2] = __float_as_uint(Qs[row0 * LSTR + kk + tg + 4]);
            a[3] = __float_as_uint(Qs[row1 * LSTR + kk + tg + 4]);
#pragma unroll
            for (int nt = 0; nt < 4; nt++) {
                int n = wn * 32 + nt * 8 + g;
                uint32_t b[2];
                b[0] = __float_as_uint(KVs[n * LSTR + kk + tg]);
                b[1] = __float_as_uint(KVs[n * LSTR + kk + tg + 4]);
                mma_tf32(sacc[nt], a, b);
            }
        }

        bool diag = (j == qt);
        float pm0 = -1e30f, pm1 = -1e30f;
#pragma unroll
        for (int nt = 0; nt < 4; nt++) {
            int cb = wn * 32 + nt * 8 + 2 * tg;
#pragma unroll
            for (int cc = 0; cc < 2; cc++) {
                float s0 = sacc[nt][cc] * scale;
                float s1 = sacc[nt][2 + cc] * scale;
                if (diag && (cb + cc) > row0) s0 = -1e30f;
                if (diag && (cb + cc) > row1) s1 = -1e30f;
                sacc[nt][cc] = s0; sacc[nt][2 + cc] = s1;
                pm0 = fmaxf(pm0, s0); pm1 = fmaxf(pm1, s1);
            }
        }
        pm0 = fmaxf(pm0, __shfl_xor_sync(0xffffffffu, pm0, 1));
        pm0 = fmaxf(pm0, __shfl_xor_sync(0xffffffffu, pm0, 2));
        pm1 = fmaxf(pm1, __shfl_xor_sync(0xffffffffu, pm1, 1));
        pm1 = fmaxf(pm1, __shfl_xor_sync(0xffffffffu, pm1, 2));
        if (tg == 0) { Smax[row0 * 2 + wn] = pm0; Smax[row1 * 2 + wn] = pm1; }
        __syncthreads();

        float mn0 = fmaxf(m0, fmaxf(Smax[row0 * 2], Smax[row0 * 2 + 1]));
        float mn1 = fmaxf(m1, fmaxf(Smax[row1 * 2], Smax[row1 * 2 + 1]));
        float fac0 = __expf(m0 - mn0), fac1 = __expf(m1 - mn1);

        float ps0 = 0.f, ps1 = 0.f;
#pragma unroll
        for (int nt = 0; nt < 4; nt++) {
            float p00 = __expf(sacc[nt][0] - mn0), p01 = __expf(sacc[nt][1] - mn0);
            float p10 = __expf(sacc[nt][2] - mn1), p11 = __expf(sacc[nt][3] - mn1);
            ps0 += p00 + p01; ps1 += p10 + p11;
            int cb = wn * 32 + nt * 8 + 2 * tg;
            *(float2*)&Ps[row0 * PSTR + cb] =
                make_float2(__uint_as_float(f2tf(p00)), __uint_as_float(f2tf(p01)));
            *(float2*)&Ps[row1 * PSTR + cb] =
                make_float2(__uint_as_float(f2tf(p10)), __uint_as_float(f2tf(p11)));
        }
        ps0 += __shfl_xor_sync(0xffffffffu, ps0, 1);
        ps0 += __shfl_xor_sync(0xffffffffu, ps0, 2);
        ps1 += __shfl_xor_sync(0xffffffffu, ps1, 1);
        ps1 += __shfl_xor_sync(0xffffffffu, ps1, 2);
        if (tg == 0) { Ssum[row0 * 2 + wn] = ps0; Ssum[row1 * 2 + wn] = ps1; }

#pragma unroll
        for (int nt = 0; nt < 8; nt++) {
            o[nt][0] *= fac0; o[nt][1] *= fac0;
            o[nt][2] *= fac1; o[nt][3] *= fac1;
        }
        m0 = mn0; m1 = mn1;
        __syncthreads();

        l0 = l0 * fac0 + Ssum[row0 * 2] + Ssum[row0 * 2 + 1];
        l1 = l1 * fac1 + Ssum[row1 * 2] + Ssum[row1 * 2 + 1];

#pragma unroll
        for (int it = 0; it < 8; it++) {
            int e = tid + it * 256;
            int r = e >> 5, c4 = (e & 31) * 4;
            *(float4*)&KVs[r * LSTR + c4] =
                *(const float4*)&V[(size_t)(j * 64 + r) * KVDIM + kvh * HD + c4];
        }
        __syncthreads();

#pragma unroll
        for (int kk = 0; kk < 64; kk += 8) {
            uint32_t a[4];
            a[0] = __float_as_uint(Ps[row0 * PSTR + kk + tg]);
            a[1] = __float_as_uint(Ps[row1 * PSTR + kk + tg]);
            a[2] = __float_as_uint(Ps[row0 * PSTR + kk + tg + 4]);
            a[3] = __float_as_uint(Ps[row1 * PSTR + kk + tg + 4]);
#pragma unroll
            for (int nt = 0; nt < 8; nt++) {
                int n = wn * 64 + nt * 8 + g;
                uint32_t b[2];
                b[0] = __float_as_uint(KVs[(kk + tg) * LSTR + n]);
                b[1] = __float_as_uint(KVs[(kk + tg + 4) * LSTR + n]);
                mma_tf32(o[nt], a, b);
            }
        }
    }

    // Epilogue: normalize + store tf32-rounded bits (feeds O-projection GEMM)
    float inv0 = 1.f / l0, inv1 = 1.f / l1;
#pragma unroll
    for (int nt = 0; nt < 8; nt++) {
        int colg = h * HD + wn * 64 + nt * 8 + 2 * tg;
        size_t r0 = (size_t)(qt * 64 + row0) * QDIM + colg;
        size_t r1 = (size_t)(qt * 64 + row1) * QDIM + colg;
        *(float2*)&O[r0] = make_float2(__uint_as_float(f2tf(o[nt][0] * inv0)),
                                       __uint_as_float(f2tf(o[nt][1] * inv0)));
        *(float2*)&O[r1] = make_float2(__uint_as_float(f2tf(o[nt][2] * inv1)),
                                       __uint_as_float(f2tf(o[nt][3] * inv1)));
    }
}

// ---------------------------------------------------------------------------
// Launch
// ---------------------------------------------------------------------------
extern "C" void kernel_launch(void* const* d_in, const int* in_sizes, int n_in,
                              void* d_out, int out_size)
{
    const int*   positions = (const int*)d_in[0];
    const float* hidden    = (const float*)d_in[1];
    const float* wq        = (const float*)d_in[2];
    const float* wk        = (const float*)d_in[3];
    const float* wv        = (const float*)d_in[4];
    const float* wo        = (const float*)d_in[5];
    const float* qnw       = (const float*)d_in[6];
    const float* knw       = (const float*)d_in[7];
    float* out = (float*)d_out;

    float *q, *k, *v, *attn, *hid, *wqR, *wkR, *wvR, *woR;
    cudaGetSymbolAddress((void**)&q, g_q);
    cudaGetSymbolAddress((void**)&k, g_k);
    cudaGetSymbolAddress((void**)&v, g_v);
    cudaGetSymbolAddress((void**)&attn, g_attn);
    cudaGetSymbolAddress((void**)&hid, g_hid);
    cudaGetSymbolAddress((void**)&wqR, g_wqR);
    cudaGetSymbolAddress((void**)&wkR, g_wkR);
    cudaGetSymbolAddress((void**)&wvR, g_wvR);
    cudaGetSymbolAddress((void**)&woR, g_woR);

    // Prep: round all GEMM inputs to tf32 once
    {
        int n;
        n = HIDDEN * QDIM / 4;  round_tf32<<<(n + 255) / 256, 256>>>(wq, wqR, n);
        n = HIDDEN * KVDIM / 4; round_tf32<<<(n + 255) / 256, 256>>>(wk, wkR, n);
        n = HIDDEN * KVDIM / 4; round_tf32<<<(n + 255) / 256, 256>>>(wv, wvR, n);
        n = QDIM * HIDDEN / 4;  round_tf32<<<(n + 255) / 256, 256>>>(wo, woR, n);
        n = TT * HIDDEN / 4;    round_tf32<<<(n + 255) / 256, 256>>>(hidden, hid, n);
    }

    // QKV projections (tf32 mma, cvt-free hot loop)
    {
        int smem = GSMEM_FLOATS * (int)sizeof(float);   // 71680
        cudaFuncSetAttribute(tf32_gemm, cudaFuncAttributeMaxDynamicSharedMemorySize, smem);
        dim3 gq(QDIM / 128, TT / 128);
        tf32_gemm<<<gq, 256, smem>>>(hid, wqR, q, TT, QDIM, HIDDEN);
        dim3 gk(KVDIM / 128, TT / 128);
        tf32_gemm<<<gk, 256, smem>>>(hid, wkR, k, TT, KVDIM, HIDDEN);
        tf32_gemm<<<gk, 256, smem>>>(hid, wvR, v, TT, KVDIM, HIDDEN);
    }

    // RMSNorm + RoPE (emits tf32-rounded q/k); round v for flash
    {
        int rows = TT * NH + TT * NKV;
        int blocks = (rows + 3) / 4;
        norm_rope_kernel<<<blocks, 128>>>(q, k, positions, qnw, knw);
        int n = TT * KVDIM / 4;
        round_tf32<<<(n + 255) / 256, 256>>>(v, v, n);
    }

    // Flash attention (tf32 mma, pre-rounded inputs)
    {
        int smem = (2 * 64 * LSTR + 64 * PSTR + 256) * (int)sizeof(float);
        cudaFuncSetAttribute(flash_tf32,
                             cudaFuncAttributeMaxDynamicSharedMemorySize, smem);
        dim3 g(TT / 64, NH);
        flash_tf32<<<g, 256, smem>>>(q, k, v, attn);
    }

    // Output projection
    {
        int smem = GSMEM_FLOATS * (int)sizeof(float);
        dim3 go(HIDDEN / 128, TT / 128);
        tf32_gemm<<<go, 256, smem>>>(attn, woR, out, TT, HIDDEN, HIDDEN);
    }
}

// round 8
// speedup vs baseline: 4.0339x; 1.0682x over previous
#include <cuda_runtime.h>
#include <math.h>
#include <stdint.h>

#define TT 2048
#define HIDDEN 4096
#define NH 32
#define NKV 8
#define HD 128
#define QDIM (NH*HD)    // 4096
#define KVDIM (NKV*HD)  // 1024

// Scratch (allocation-free rule: __device__ globals)
__device__ float g_q[TT*QDIM];
__device__ float g_k[TT*KVDIM];
__device__ float g_v[TT*KVDIM];
__device__ float g_attn[TT*QDIM];        // tf32-rounded (flash epilogue)
__device__ float g_hid[TT*HIDDEN];       // tf32-rounded hidden
__device__ float g_wqR[HIDDEN*QDIM];     // tf32-rounded weights
__device__ float g_wkR[HIDDEN*KVDIM];
__device__ float g_wvR[HIDDEN*KVDIM];
__device__ float g_woR[QDIM*HIDDEN];

// ---------------------------------------------------------------------------
// Helpers
// ---------------------------------------------------------------------------
__device__ __forceinline__ uint32_t f2tf(float x) {
    uint32_t r;
    asm("cvt.rna.tf32.f32 %0, %1;" : "=r"(r) : "f"(x));
    return r;
}

__device__ __forceinline__ void mma_tf32(float* c, const uint32_t* a, const uint32_t* b) {
    asm volatile(
        "mma.sync.aligned.m16n8k8.row.col.f32.tf32.tf32.f32 "
        "{%0,%1,%2,%3}, {%4,%5,%6,%7}, {%8,%9}, {%0,%1,%2,%3};"
        : "+f"(c[0]), "+f"(c[1]), "+f"(c[2]), "+f"(c[3])
        : "r"(a[0]), "r"(a[1]), "r"(a[2]), "r"(a[3]), "r"(b[0]), "r"(b[1]));
}

__device__ __forceinline__ void cp16(void* smem_dst, const void* gsrc) {
    uint32_t d = (uint32_t)__cvta_generic_to_shared(smem_dst);
    asm volatile("cp.async.cg.shared.global [%0], [%1], 16;" :: "r"(d), "l"(gsrc));
}
__device__ __forceinline__ void cp_commit() { asm volatile("cp.async.commit_group;"); }
template<int N> __device__ __forceinline__ void cp_wait() {
    asm volatile("cp.async.wait_group %0;" :: "n"(N));
}

// ---------------------------------------------------------------------------
// Prep: elementwise tf32 rounding
// ---------------------------------------------------------------------------
__global__ void round_tf32(const float* __restrict__ src, float* __restrict__ dst, int n4)
{
    int i = blockIdx.x * blockDim.x + threadIdx.x;
    if (i >= n4) return;
    float4 v = ((const float4*)src)[i];
    ((float4*)dst)[i] = make_float4(
        __uint_as_float(f2tf(v.x)), __uint_as_float(f2tf(v.y)),
        __uint_as_float(f2tf(v.z)), __uint_as_float(f2tf(v.w)));
}

// ---------------------------------------------------------------------------
// TF32 tensor-core GEMM: C[M,N] = A[M,K] @ B[K,N], row-major, pre-rounded.
// 128x128 CTA tile, BK=32, 128 threads (4 warps as 2x2, warp tile 64x64,
// mt=4 x nt=8 -> 1.0 LDS per MMA). Double-buffered cp.async.
// ---------------------------------------------------------------------------
#define GAS 36    // As k-stride: (36m+k)%32=(4m+k)%32 -> frag reads conflict-free
#define GBS 136   // Bs n-stride: (136k+n)%32=(8k+n)%32 -> frag reads conflict-free
#define GSMEM_FLOATS (2*128*GAS + 2*32*GBS)

__global__ __launch_bounds__(128, 2)
void tf32_gemm(const float* __restrict__ A, const float* __restrict__ B,
               float* __restrict__ C, int M, int N, int K)
{
    extern __shared__ float smem[];
    float (*As)[128][GAS] = (float(*)[128][GAS])smem;              // [2][128][36]
    float (*Bs)[32][GBS]  = (float(*)[32][GBS])(smem + 2*128*GAS); // [2][32][136]

    int bm = blockIdx.y * 128, bn = blockIdx.x * 128;
    int tid = threadIdx.x;
    int w = tid >> 5, lane = tid & 31, g = lane >> 2, tg = lane & 3;
    int wm = (w >> 1) * 64, wn = (w & 1) * 64;

    float acc[4][8][4];
#pragma unroll
    for (int mt = 0; mt < 4; mt++)
#pragma unroll
        for (int nt = 0; nt < 8; nt++)
#pragma unroll
            for (int i = 0; i < 4; i++) acc[mt][nt][i] = 0.f;

    int ntile = K / 32;

    auto issue = [&](int t) {
        int s = t & 1;
        size_t k0 = (size_t)t * 32;
#pragma unroll
        for (int i = 0; i < 8; i++) {
            int e = tid + i * 128;
            int ar = e >> 3, ac = (e & 7) * 4;
            cp16(&As[s][ar][ac], &A[(size_t)(bm + ar) * K + k0 + ac]);
            int br = e >> 5, bc = (e & 31) * 4;
            cp16(&Bs[s][br][bc], &B[(size_t)(k0 + br) * N + bn + bc]);
        }
        cp_commit();
    };

    issue(0);

    for (int t = 0; t < ntile; t++) {
        if (t + 1 < ntile) { issue(t + 1); cp_wait<1>(); }
        else               { cp_wait<0>(); }
        __syncthreads();

        const float (*as)[GAS] = As[t & 1];
        const float (*bs)[GBS] = Bs[t & 1];
#pragma unroll
        for (int kk = 0; kk < 32; kk += 8) {
            uint32_t af[4][4];
#pragma unroll
            for (int mt = 0; mt < 4; mt++) {
                int m = wm + mt * 16 + g;
                af[mt][0] = __float_as_uint(as[m][kk + tg]);
                af[mt][1] = __float_as_uint(as[m + 8][kk + tg]);
                af[mt][2] = __float_as_uint(as[m][kk + tg + 4]);
                af[mt][3] = __float_as_uint(as[m + 8][kk + tg + 4]);
            }
            uint32_t bf[8][2];
#pragma unroll
            for (int nt = 0; nt < 8; nt++) {
                int n = wn + nt * 8 + g;
                bf[nt][0] = __float_as_uint(bs[kk + tg][n]);
                bf[nt][1] = __float_as_uint(bs[kk + tg + 4][n]);
            }
#pragma unroll
            for (int mt = 0; mt < 4; mt++)
#pragma unroll
                for (int nt = 0; nt < 8; nt++)
                    mma_tf32(acc[mt][nt], af[mt], bf[nt]);
        }
        __syncthreads();
    }

#pragma unroll
    for (int mt = 0; mt < 4; mt++)
#pragma unroll
        for (int nt = 0; nt < 8; nt++) {
            size_t r0 = (size_t)(bm + wm + mt * 16 + g) * N + bn + wn + nt * 8 + 2 * tg;
            size_t r1 = r0 + (size_t)8 * N;
            *(float2*)&C[r0] = make_float2(acc[mt][nt][0], acc[mt][nt][1]);
            *(float2*)&C[r1] = make_float2(acc[mt][nt][2], acc[mt][nt][3]);
        }
}

// ---------------------------------------------------------------------------
// Fused RMSNorm + RoPE; outputs tf32-rounded bits
// ---------------------------------------------------------------------------
__global__ void norm_rope_kernel(float* __restrict__ q, float* __restrict__ k,
                                 const int* __restrict__ positions,
                                 const float* __restrict__ qw,
                                 const float* __restrict__ kw)
{
    const int QROWS = TT * NH;
    const int TOTAL = QROWS + TT * NKV;
    int row = blockIdx.x * (blockDim.x >> 5) + (threadIdx.x >> 5);
    if (row >= TOTAL) return;
    int lane = threadIdx.x & 31;

    float* x;
    const float* w;
    int t;
    if (row < QROWS) {
        t = row / NH;
        x = q + (size_t)row * HD;
        w = qw;
    } else {
        int r2 = row - QROWS;
        t = r2 / NKV;
        x = k + (size_t)r2 * HD;
        w = kw;
    }

    float x0 = x[lane], x1 = x[lane + 32], x2 = x[lane + 64], x3 = x[lane + 96];

    float ss = x0 * x0 + x1 * x1 + x2 * x2 + x3 * x3;
#pragma unroll
    for (int m = 16; m; m >>= 1) ss += __shfl_xor_sync(0xffffffffu, ss, m);

    float rinv = rsqrtf(ss * (1.0f / 128.0f) + 1e-6f);
    x0 *= rinv * w[lane];
    x1 *= rinv * w[lane + 32];
    x2 *= rinv * w[lane + 64];
    x3 *= rinv * w[lane + 96];

    float p = (float)positions[t];
    float invf0 = powf(10000.0f, -(float)lane * (1.0f / 64.0f));
    float invf1 = powf(10000.0f, -(float)(lane + 32) * (1.0f / 64.0f));
    float f0 = p * invf0, f1 = p * invf1;
    float c0 = cosf(f0), s0 = sinf(f0);
    float c1 = cosf(f1), s1 = sinf(f1);

    x[lane]      = __uint_as_float(f2tf(x0 * c0 - x2 * s0));
    x[lane + 64] = __uint_as_float(f2tf(x2 * c0 + x0 * s0));
    x[lane + 32] = __uint_as_float(f2tf(x1 * c1 - x3 * s1));
    x[lane + 96] = __uint_as_float(f2tf(x3 * c1 + x1 * s1));
}

// ---------------------------------------------------------------------------
// Causal flash attention, tf32 mma; inputs pre-rounded
// ---------------------------------------------------------------------------
#define LSTR 132
#define PSTR 68

__global__ __launch_bounds__(256, 2)
void flash_tf32(const float* __restrict__ Q, const float* __restrict__ K,
                const float* __restrict__ V, float* __restrict__ O)
{
    extern __shared__ float sm[];
    float* Qs   = sm;
    float* KVs  = Qs + 64 * LSTR;
    float* Ps   = KVs + 64 * LSTR;
    float* Smax = Ps + 64 * PSTR;
    float* Ssum = Smax + 128;

    int qt = blockIdx.x;
    int h  = blockIdx.y;
    int kvh = h >> 2;
    int tid = threadIdx.x;
    int w = tid >> 5, lane = tid & 31, g = lane >> 2, tg = lane & 3;
    int wm = (w >> 1) * 16;
    int wn = w & 1;

#pragma unroll
    for (int it = 0; it < 8; it++) {
        int e = tid + it * 256;
        int r = e >> 5, c4 = (e & 31) * 4;
        *(float4*)&Qs[r * LSTR + c4] =
            *(const float4*)&Q[(size_t)(qt * 64 + r) * QDIM + h * HD + c4];
    }

    float m0 = -1e30f, m1 = -1e30f, l0 = 0.f, l1 = 0.f;
    float o[8][4];
#pragma unroll
    for (int nt = 0; nt < 8; nt++)
#pragma unroll
        for (int i = 0; i < 4; i++) o[nt][i] = 0.f;

    const float scale = 0.08838834764831845f;
    int row0 = wm + g, row1 = wm + g + 8;

    for (int j = 0; j <= qt; j++) {
        __syncthreads();
#pragma unroll
        for (int it = 0; it < 8; it++) {
            int e = tid + it * 256;
            int r = e >> 5, c4 = (e & 31) * 4;
            *(float4*)&KVs[r * LSTR + c4] =
                *(const float4*)&K[(size_t)(j * 64 + r) * KVDIM + kvh * HD + c4];
        }
        __syncthreads();

        float sacc[4][4];
#pragma unroll
        for (int nt = 0; nt < 4; nt++)
#pragma unroll
            for (int i = 0; i < 4; i++) sacc[nt][i] = 0.f;

#pragma unroll
        for (int kk = 0; kk < HD; kk += 8) {
            uint32_t a[4];
            a[0] = __float_as_uint(Qs[row0 * LSTR + kk + tg]);
            a[1] = __float_as_uint(Qs[row1 * LSTR + kk + tg]);
            a[2] = __float_as_uint(Qs[row0 * LSTR + kk + tg + 4]);
            a[3] = __float_as_uint(Qs[row1 * LSTR + kk + tg + 4]);
#pragma unroll
            for (int nt = 0; nt < 4; nt++) {
                int n = wn * 32 + nt * 8 + g;
                uint32_t b[2];
                b[0] = __float_as_uint(KVs[n * LSTR + kk + tg]);
                b[1] = __float_as_uint(KVs[n * LSTR + kk + tg + 4]);
                mma_tf32(sacc[nt], a, b);
            }
        }

        bool diag = (j == qt);
        float pm0 = -1e30f, pm1 = -1e30f;
#pragma unroll
        for (int nt = 0; nt < 4; nt++) {
            int cb = wn * 32 + nt * 8 + 2 * tg;
#pragma unroll
            for (int cc = 0; cc < 2; cc++) {
                float s0 = sacc[nt][cc] * scale;
                float s1 = sacc[nt][2 + cc] * scale;
                if (diag && (cb + cc) > row0) s0 = -1e30f;
                if (diag && (cb + cc) > row1) s1 = -1e30f;
                sacc[nt][cc] = s0; sacc[nt][2 + cc] = s1;
                pm0 = fmaxf(pm0, s0); pm1 = fmaxf(pm1, s1);
            }
        }
        pm0 = fmaxf(pm0, __shfl_xor_sync(0xffffffffu, pm0, 1));
        pm0 = fmaxf(pm0, __shfl_xor_sync(0xffffffffu, pm0, 2));
        pm1 = fmaxf(pm1, __shfl_xor_sync(0xffffffffu, pm1, 1));
        pm1 = fmaxf(pm1, __shfl_xor_sync(0xffffffffu, pm1, 2));
        if (tg == 0) { Smax[row0 * 2 + wn] = pm0; Smax[row1 * 2 + wn] = pm1; }
        __syncthreads();

        float mn0 = fmaxf(m0, fmaxf(Smax[row0 * 2], Smax[row0 * 2 + 1]));
        float mn1 = fmaxf(m1, fmaxf(Smax[row1 * 2], Smax[row1 * 2 + 1]));
        float fac0 = __expf(m0 - mn0), fac1 = __expf(m1 - mn1);

        float ps0 = 0.f, ps1 = 0.f;
#pragma unroll
        for (int nt = 0; nt < 4; nt++) {
            float p00 = __expf(sacc[nt][0] - mn0), p01 = __expf(sacc[nt][1] - mn0);
            float p10 = __expf(sacc[nt][2] - mn1), p11 = __expf(sacc[nt][3] - mn1);
            ps0 += p00 + p01; ps1 += p10 + p11;
            int cb = wn * 32 + nt * 8 + 2 * tg;
            *(float2*)&Ps[row0 * PSTR + cb] =
                make_float2(__uint_as_float(f2tf(p00)), __uint_as_float(f2tf(p01)));
            *(float2*)&Ps[row1 * PSTR + cb] =
                make_float2(__uint_as_float(f2tf(p10)), __uint_as_float(f2tf(p11)));
        }
        ps0 += __shfl_xor_sync(0xffffffffu, ps0, 1);
        ps0 += __shfl_xor_sync(0xffffffffu, ps0, 2);
        ps1 += __shfl_xor_sync(0xffffffffu, ps1, 1);
        ps1 += __shfl_xor_sync(0xffffffffu, ps1, 2);
        if (tg == 0) { Ssum[row0 * 2 + wn] = ps0; Ssum[row1 * 2 + wn] = ps1; }

#pragma unroll
        for (int nt = 0; nt < 8; nt++) {
            o[nt][0] *= fac0; o[nt][1] *= fac0;
            o[nt][2] *= fac1; o[nt][3] *= fac1;
        }
        m0 = mn0; m1 = mn1;
        __syncthreads();

        l0 = l0 * fac0 + Ssum[row0 * 2] + Ssum[row0 * 2 + 1];
        l1 = l1 * fac1 + Ssum[row1 * 2] + Ssum[row1 * 2 + 1];

#pragma unroll
        for (int it = 0; it < 8; it++) {
            int e = tid + it * 256;
            int r = e >> 5, c4 = (e & 31) * 4;
            *(float4*)&KVs[r * LSTR + c4] =
                *(const float4*)&V[(size_t)(j * 64 + r) * KVDIM + kvh * HD + c4];
        }
        __syncthreads();

#pragma unroll
        for (int kk = 0; kk < 64; kk += 8) {
            uint32_t a[4];
            a[0] = __float_as_uint(Ps[row0 * PSTR + kk + tg]);
            a[1] = __float_as_uint(Ps[row1 * PSTR + kk + tg]);
            a[2] = __float_as_uint(Ps[row0 * PSTR + kk + tg + 4]);
            a[3] = __float_as_uint(Ps[row1 * PSTR + kk + tg + 4]);
#pragma unroll
            for (int nt = 0; nt < 8; nt++) {
                int n = wn * 64 + nt * 8 + g;
                uint32_t b[2];
                b[0] = __float_as_uint(KVs[(kk + tg) * LSTR + n]);
                b[1] = __float_as_uint(KVs[(kk + tg + 4) * LSTR + n]);
                mma_tf32(o[nt], a, b);
            }
        }
    }

    float inv0 = 1.f / l0, inv1 = 1.f / l1;
#pragma unroll
    for (int nt = 0; nt < 8; nt++) {
        int colg = h * HD + wn * 64 + nt * 8 + 2 * tg;
        size_t r0 = (size_t)(qt * 64 + row0) * QDIM + colg;
        size_t r1 = (size_t)(qt * 64 + row1) * QDIM + colg;
        *(float2*)&O[r0] = make_float2(__uint_as_float(f2tf(o[nt][0] * inv0)),
                                       __uint_as_float(f2tf(o[nt][1] * inv0)));
        *(float2*)&O[r1] = make_float2(__uint_as_float(f2tf(o[nt][2] * inv1)),
                                       __uint_as_float(f2tf(o[nt][3] * inv1)));
    }
}

// ---------------------------------------------------------------------------
// Launch
// ---------------------------------------------------------------------------
extern "C" void kernel_launch(void* const* d_in, const int* in_sizes, int n_in,
                              void* d_out, int out_size)
{
    const int*   positions = (const int*)d_in[0];
    const float* hidden    = (const float*)d_in[1];
    const float* wq        = (const float*)d_in[2];
    const float* wk        = (const float*)d_in[3];
    const float* wv        = (const float*)d_in[4];
    const float* wo        = (const float*)d_in[5];
    const float* qnw       = (const float*)d_in[6];
    const float* knw       = (const float*)d_in[7];
    float* out = (float*)d_out;

    float *q, *k, *v, *attn, *hid, *wqR, *wkR, *wvR, *woR;
    cudaGetSymbolAddress((void**)&q, g_q);
    cudaGetSymbolAddress((void**)&k, g_k);
    cudaGetSymbolAddress((void**)&v, g_v);
    cudaGetSymbolAddress((void**)&attn, g_attn);
    cudaGetSymbolAddress((void**)&hid, g_hid);
    cudaGetSymbolAddress((void**)&wqR, g_wqR);
    cudaGetSymbolAddress((void**)&wkR, g_wkR);
    cudaGetSymbolAddress((void**)&wvR, g_wvR);
    cudaGetSymbolAddress((void**)&woR, g_woR);

    // Prep: round all GEMM inputs to tf32 once
    {
        int n;
        n = HIDDEN * QDIM / 4;  round_tf32<<<(n + 255) / 256, 256>>>(wq, wqR, n);
        n = HIDDEN * KVDIM / 4; round_tf32<<<(n + 255) / 256, 256>>>(wk, wkR, n);
        n = HIDDEN * KVDIM / 4; round_tf32<<<(n + 255) / 256, 256>>>(wv, wvR, n);
        n = QDIM * HIDDEN / 4;  round_tf32<<<(n + 255) / 256, 256>>>(wo, woR, n);
        n = TT * HIDDEN / 4;    round_tf32<<<(n + 255) / 256, 256>>>(hidden, hid, n);
    }

    // QKV projections
    {
        int smem = GSMEM_FLOATS * (int)sizeof(float);   // 71680
        cudaFuncSetAttribute(tf32_gemm, cudaFuncAttributeMaxDynamicSharedMemorySize, smem);
        dim3 gq(QDIM / 128, TT / 128);
        tf32_gemm<<<gq, 128, smem>>>(hid, wqR, q, TT, QDIM, HIDDEN);
        dim3 gk(KVDIM / 128, TT / 128);
        tf32_gemm<<<gk, 128, smem>>>(hid, wkR, k, TT, KVDIM, HIDDEN);
        tf32_gemm<<<gk, 128, smem>>>(hid, wvR, v, TT, KVDIM, HIDDEN);
    }

    // RMSNorm + RoPE (emits tf32-rounded q/k); round v for flash
    {
        int rows = TT * NH + TT * NKV;
        int blocks = (rows + 3) / 4;
        norm_rope_kernel<<<blocks, 128>>>(q, k, positions, qnw, knw);
        int n = TT * KVDIM / 4;
        round_tf32<<<(n + 255) / 256, 256>>>(v, v, n);
    }

    // Flash attention
    {
        int smem = (2 * 64 * LSTR + 64 * PSTR + 256) * (int)sizeof(float);
        cudaFuncSetAttribute(flash_tf32,
                             cudaFuncAttributeMaxDynamicSharedMemorySize, smem);
        dim3 g(TT / 64, NH);
        flash_tf32<<<g, 256, smem>>>(q, k, v, attn);
    }

    // Output projection
    {
        int smem = GSMEM_FLOATS * (int)sizeof(float);
        dim3 go(HIDDEN / 128, TT / 128);
        tf32_gemm<<<go, 128, smem>>>(attn, woR, out, TT, HIDDEN, HIDDEN);
    }
}

// round 9
// speedup vs baseline: 4.0436x; 1.0024x over previous
#include <cuda_runtime.h>
#include <math.h>
#include <stdint.h>

#define TT 2048
#define HIDDEN 4096
#define NH 32
#define NKV 8
#define HD 128
#define QDIM (NH*HD)    // 4096
#define KVDIM (NKV*HD)  // 1024

// Scratch (allocation-free rule: __device__ globals)
__device__ float g_q[TT*QDIM];
__device__ float g_k[TT*KVDIM];
__device__ float g_v[TT*KVDIM];
__device__ float g_attn[TT*QDIM];        // tf32-rounded (flash epilogue)
__device__ float g_hid[TT*HIDDEN];       // tf32-rounded hidden
__device__ float g_wqR[HIDDEN*QDIM];     // tf32-rounded weights
__device__ float g_wkR[HIDDEN*KVDIM];
__device__ float g_wvR[HIDDEN*KVDIM];
__device__ float g_woR[QDIM*HIDDEN];

// ---------------------------------------------------------------------------
// Helpers
// ---------------------------------------------------------------------------
__device__ __forceinline__ uint32_t f2tf(float x) {
    uint32_t r;
    asm("cvt.rna.tf32.f32 %0, %1;" : "=r"(r) : "f"(x));
    return r;
}

__device__ __forceinline__ void mma_tf32(float* c, const uint32_t* a, const uint32_t* b) {
    asm volatile(
        "mma.sync.aligned.m16n8k8.row.col.f32.tf32.tf32.f32 "
        "{%0,%1,%2,%3}, {%4,%5,%6,%7}, {%8,%9}, {%0,%1,%2,%3};"
        : "+f"(c[0]), "+f"(c[1]), "+f"(c[2]), "+f"(c[3])
        : "r"(a[0]), "r"(a[1]), "r"(a[2]), "r"(a[3]), "r"(b[0]), "r"(b[1]));
}

__device__ __forceinline__ void cp16(void* smem_dst, const void* gsrc) {
    uint32_t d = (uint32_t)__cvta_generic_to_shared(smem_dst);
    asm volatile("cp.async.cg.shared.global [%0], [%1], 16;" :: "r"(d), "l"(gsrc));
}
__device__ __forceinline__ void cp_commit() { asm volatile("cp.async.commit_group;"); }
template<int N> __device__ __forceinline__ void cp_wait() {
    asm volatile("cp.async.wait_group %0;" :: "n"(N));
}

// ---------------------------------------------------------------------------
// Prep: elementwise tf32 rounding
// ---------------------------------------------------------------------------
__global__ void round_tf32(const float* __restrict__ src, float* __restrict__ dst, int n4)
{
    int i = blockIdx.x * blockDim.x + threadIdx.x;
    if (i >= n4) return;
    float4 v = ((const float4*)src)[i];
    ((float4*)dst)[i] = make_float4(
        __uint_as_float(f2tf(v.x)), __uint_as_float(f2tf(v.y)),
        __uint_as_float(f2tf(v.z)), __uint_as_float(f2tf(v.w)));
}

// ---------------------------------------------------------------------------
// TF32 tensor-core GEMM: C[M,N] = A[M,K] @ B[K,N], row-major, pre-rounded.
// 128x128 CTA tile, BK=32, 128 threads (4 warps as 2x2, warp tile 64x64,
// mt=4 x nt=8 -> 1.0 LDS per MMA). Double-buffered cp.async.
// ---------------------------------------------------------------------------
#define GAS 36    // As k-stride: (36m+k)%32=(4m+k)%32 -> frag reads conflict-free
#define GBS 136   // Bs n-stride: (136k+n)%32=(8k+n)%32 -> frag reads conflict-free
#define GSMEM_FLOATS (2*128*GAS + 2*32*GBS)

__global__ __launch_bounds__(128, 2)
void tf32_gemm(const float* __restrict__ A, const float* __restrict__ B,
               float* __restrict__ C, int M, int N, int K)
{
    extern __shared__ float smem[];
    float (*As)[128][GAS] = (float(*)[128][GAS])smem;              // [2][128][36]
    float (*Bs)[32][GBS]  = (float(*)[32][GBS])(smem + 2*128*GAS); // [2][32][136]

    int bm = blockIdx.y * 128, bn = blockIdx.x * 128;
    int tid = threadIdx.x;
    int w = tid >> 5, lane = tid & 31, g = lane >> 2, tg = lane & 3;
    int wm = (w >> 1) * 64, wn = (w & 1) * 64;

    float acc[4][8][4];
#pragma unroll
    for (int mt = 0; mt < 4; mt++)
#pragma unroll
        for (int nt = 0; nt < 8; nt++)
#pragma unroll
            for (int i = 0; i < 4; i++) acc[mt][nt][i] = 0.f;

    int ntile = K / 32;

    auto issue = [&](int t) {
        int s = t & 1;
        size_t k0 = (size_t)t * 32;
#pragma unroll
        for (int i = 0; i < 8; i++) {
            int e = tid + i * 128;
            int ar = e >> 3, ac = (e & 7) * 4;
            cp16(&As[s][ar][ac], &A[(size_t)(bm + ar) * K + k0 + ac]);
            int br = e >> 5, bc = (e & 31) * 4;
            cp16(&Bs[s][br][bc], &B[(size_t)(k0 + br) * N + bn + bc]);
        }
        cp_commit();
    };

    issue(0);

    for (int t = 0; t < ntile; t++) {
        if (t + 1 < ntile) { issue(t + 1); cp_wait<1>(); }
        else               { cp_wait<0>(); }
        __syncthreads();

        const float (*as)[GAS] = As[t & 1];
        const float (*bs)[GBS] = Bs[t & 1];
#pragma unroll
        for (int kk = 0; kk < 32; kk += 8) {
            uint32_t af[4][4];
#pragma unroll
            for (int mt = 0; mt < 4; mt++) {
                int m = wm + mt * 16 + g;
                af[mt][0] = __float_as_uint(as[m][kk + tg]);
                af[mt][1] = __float_as_uint(as[m + 8][kk + tg]);
                af[mt][2] = __float_as_uint(as[m][kk + tg + 4]);
                af[mt][3] = __float_as_uint(as[m + 8][kk + tg + 4]);
            }
            uint32_t bf[8][2];
#pragma unroll
            for (int nt = 0; nt < 8; nt++) {
                int n = wn + nt * 8 + g;
                bf[nt][0] = __float_as_uint(bs[kk + tg][n]);
                bf[nt][1] = __float_as_uint(bs[kk + tg + 4][n]);
            }
#pragma unroll
            for (int mt = 0; mt < 4; mt++)
#pragma unroll
                for (int nt = 0; nt < 8; nt++)
                    mma_tf32(acc[mt][nt], af[mt], bf[nt]);
        }
        __syncthreads();
    }

#pragma unroll
    for (int mt = 0; mt < 4; mt++)
#pragma unroll
        for (int nt = 0; nt < 8; nt++) {
            size_t r0 = (size_t)(bm + wm + mt * 16 + g) * N + bn + wn + nt * 8 + 2 * tg;
            size_t r1 = r0 + (size_t)8 * N;
            *(float2*)&C[r0] = make_float2(acc[mt][nt][0], acc[mt][nt][1]);
            *(float2*)&C[r1] = make_float2(acc[mt][nt][2], acc[mt][nt][3]);
        }
}

// ---------------------------------------------------------------------------
// Fused RMSNorm + RoPE; outputs tf32-rounded bits
// ---------------------------------------------------------------------------
__global__ void norm_rope_kernel(float* __restrict__ q, float* __restrict__ k,
                                 const int* __restrict__ positions,
                                 const float* __restrict__ qw,
                                 const float* __restrict__ kw)
{
    const int QROWS = TT * NH;
    const int TOTAL = QROWS + TT * NKV;
    int row = blockIdx.x * (blockDim.x >> 5) + (threadIdx.x >> 5);
    if (row >= TOTAL) return;
    int lane = threadIdx.x & 31;

    float* x;
    const float* w;
    int t;
    if (row < QROWS) {
        t = row / NH;
        x = q + (size_t)row * HD;
        w = qw;
    } else {
        int r2 = row - QROWS;
        t = r2 / NKV;
        x = k + (size_t)r2 * HD;
        w = kw;
    }

    float x0 = x[lane], x1 = x[lane + 32], x2 = x[lane + 64], x3 = x[lane + 96];

    float ss = x0 * x0 + x1 * x1 + x2 * x2 + x3 * x3;
#pragma unroll
    for (int m = 16; m; m >>= 1) ss += __shfl_xor_sync(0xffffffffu, ss, m);

    float rinv = rsqrtf(ss * (1.0f / 128.0f) + 1e-6f);
    x0 *= rinv * w[lane];
    x1 *= rinv * w[lane + 32];
    x2 *= rinv * w[lane + 64];
    x3 *= rinv * w[lane + 96];

    float p = (float)positions[t];
    float invf0 = powf(10000.0f, -(float)lane * (1.0f / 64.0f));
    float invf1 = powf(10000.0f, -(float)(lane + 32) * (1.0f / 64.0f));
    float f0 = p * invf0, f1 = p * invf1;
    float c0 = cosf(f0), s0 = sinf(f0);
    float c1 = cosf(f1), s1 = sinf(f1);

    x[lane]      = __uint_as_float(f2tf(x0 * c0 - x2 * s0));
    x[lane + 64] = __uint_as_float(f2tf(x2 * c0 + x0 * s0));
    x[lane + 32] = __uint_as_float(f2tf(x1 * c1 - x3 * s1));
    x[lane + 96] = __uint_as_float(f2tf(x3 * c1 + x1 * s1));
}

// ---------------------------------------------------------------------------
// Causal flash attention, tf32 mma; inputs pre-rounded
// ---------------------------------------------------------------------------
#define LSTR 132
#define PSTR 68

__global__ __launch_bounds__(256, 2)
void flash_tf32(const float* __restrict__ Q, const float* __restrict__ K,
                const float* __restrict__ V, float* __restrict__ O)
{
    extern __shared__ float sm[];
    float* Qs   = sm;
    float* KVs  = Qs + 64 * LSTR;
    float* Ps   = KVs + 64 * LSTR;
    float* Smax = Ps + 64 * PSTR;
    float* Ssum = Smax + 128;

    int qt = blockIdx.x;
    int h  = blockIdx.y;
    int kvh = h >> 2;
    int tid = threadIdx.x;
    int w = tid >> 5, lane = tid & 31, g = lane >> 2, tg = lane & 3;
    int wm = (w >> 1) * 16;
    int wn = w & 1;

#pragma unroll
    for (int it = 0; it < 8; it++) {
        int e = tid + it * 256;
        int r = e >> 5, c4 = (e & 31) * 4;
        *(float4*)&Qs[r * LSTR + c4] =
            *(const float4*)&Q[(size_t)(qt * 64 + r) * QDIM + h * HD + c4];
    }

    float m0 = -1e30f, m1 = -1e30f, l0 = 0.f, l1 = 0.f;
    float o[8][4];
#pragma unroll
    for (int nt = 0; nt < 8; nt++)
#pragma unroll
        for (int i = 0; i < 4; i++) o[nt][i] = 0.f;

    const float scale = 0.08838834764831845f;
    int row0 = wm + g, row1 = wm + g + 8;

    for (int j = 0; j <= qt; j++) {
        __syncthreads();
#pragma unroll
        for (int it = 0; it < 8; it++) {
            int e = tid + it * 256;
            int r = e >> 5, c4 = (e & 31) * 4;
            *(float4*)&KVs[r * LSTR + c4] =
                *(const float4*)&K[(size_t)(j * 64 + r) * KVDIM + kvh * HD + c4];
        }
        __syncthreads();

        float sacc[4][4];
#pragma unroll
        for (int nt = 0; nt < 4; nt++)
#pragma unroll
            for (int i = 0; i < 4; i++) sacc[nt][i] = 0.f;

#pragma unroll
        for (int kk = 0; kk < HD; kk += 8) {
            uint32_t a[4];
            a[0] = __float_as_uint(Qs[row0 * LSTR + kk + tg]);
            a[1] = __float_as_uint(Qs[row1 * LSTR + kk + tg]);
            a[2] = __float_as_uint(Qs[row0 * LSTR + kk + tg + 4]);
            a[3] = __float_as_uint(Qs[row1 * LSTR + kk + tg + 4]);
#pragma unroll
            for (int nt = 0; nt < 4; nt++) {
                int n = wn * 32 + nt * 8 + g;
                uint32_t b[2];
                b[0] = __float_as_uint(KVs[n * LSTR + kk + tg]);
                b[1] = __float_as_uint(KVs[n * LSTR + kk + tg + 4]);
                mma_tf32(sacc[nt], a, b);
            }
        }

        bool diag = (j == qt);
        float pm0 = -1e30f, pm1 = -1e30f;
#pragma unroll
        for (int nt = 0; nt < 4; nt++) {
            int cb = wn * 32 + nt * 8 + 2 * tg;
#pragma unroll
            for (int cc = 0; cc < 2; cc++) {
                float s0 = sacc[nt][cc] * scale;
                float s1 = sacc[nt][2 + cc] * scale;
                if (diag && (cb + cc) > row0) s0 = -1e30f;
                if (diag && (cb + cc) > row1) s1 = -1e30f;
                sacc[nt][cc] = s0; sacc[nt][2 + cc] = s1;
                pm0 = fmaxf(pm0, s0); pm1 = fmaxf(pm1, s1);
            }
        }
        pm0 = fmaxf(pm0, __shfl_xor_sync(0xffffffffu, pm0, 1));
        pm0 = fmaxf(pm0, __shfl_xor_sync(0xffffffffu, pm0, 2));
        pm1 = fmaxf(pm1, __shfl_xor_sync(0xffffffffu, pm1, 1));
        pm1 = fmaxf(pm1, __shfl_xor_sync(0xffffffffu, pm1, 2));
        if (tg == 0) { Smax[row0 * 2 + wn] = pm0; Smax[row1 * 2 + wn] = pm1; }
        __syncthreads();

        float mn0 = fmaxf(m0, fmaxf(Smax[row0 * 2], Smax[row0 * 2 + 1]));
        float mn1 = fmaxf(m1, fmaxf(Smax[row1 * 2], Smax[row1 * 2 + 1]));
        float fac0 = __expf(m0 - mn0), fac1 = __expf(m1 - mn1);

        float ps0 = 0.f, ps1 = 0.f;
#pragma unroll
        for (int nt = 0; nt < 4; nt++) {
            float p00 = __expf(sacc[nt][0] - mn0), p01 = __expf(sacc[nt][1] - mn0);
            float p10 = __expf(sacc[nt][2] - mn1), p11 = __expf(sacc[nt][3] - mn1);
            ps0 += p00 + p01; ps1 += p10 + p11;
            int cb = wn * 32 + nt * 8 + 2 * tg;
            *(float2*)&Ps[row0 * PSTR + cb] =
                make_float2(__uint_as_float(f2tf(p00)), __uint_as_float(f2tf(p01)));
            *(float2*)&Ps[row1 * PSTR + cb] =
                make_float2(__uint_as_float(f2tf(p10)), __uint_as_float(f2tf(p11)));
        }
        ps0 += __shfl_xor_sync(0xffffffffu, ps0, 1);
        ps0 += __shfl_xor_sync(0xffffffffu, ps0, 2);
        ps1 += __shfl_xor_sync(0xffffffffu, ps1, 1);
        ps1 += __shfl_xor_sync(0xffffffffu, ps1, 2);
        if (tg == 0) { Ssum[row0 * 2 + wn] = ps0; Ssum[row1 * 2 + wn] = ps1; }

#pragma unroll
        for (int nt = 0; nt < 8; nt++) {
            o[nt][0] *= fac0; o[nt][1] *= fac0;
            o[nt][2] *= fac1; o[nt][3] *= fac1;
        }
        m0 = mn0; m1 = mn1;
        __syncthreads();

        l0 = l0 * fac0 + Ssum[row0 * 2] + Ssum[row0 * 2 + 1];
        l1 = l1 * fac1 + Ssum[row1 * 2] + Ssum[row1 * 2 + 1];

#pragma unroll
        for (int it = 0; it < 8; it++) {
            int e = tid + it * 256;
            int r = e >> 5, c4 = (e & 31) * 4;
            *(float4*)&KVs[r * LSTR + c4] =
                *(const float4*)&V[(size_t)(j * 64 + r) * KVDIM + kvh * HD + c4];
        }
        __syncthreads();

#pragma unroll
        for (int kk = 0; kk < 64; kk += 8) {
            uint32_t a[4];
            a[0] = __float_as_uint(Ps[row0 * PSTR + kk + tg]);
            a[1] = __float_as_uint(Ps[row1 * PSTR + kk + tg]);
            a[2] = __float_as_uint(Ps[row0 * PSTR + kk + tg + 4]);
            a[3] = __float_as_uint(Ps[row1 * PSTR + kk + tg + 4]);
#pragma unroll
            for (int nt = 0; nt < 8; nt++) {
                int n = wn * 64 + nt * 8 + g;
                uint32_t b[2];
                b[0] = __float_as_uint(KVs[(kk + tg) * LSTR + n]);
                b[1] = __float_as_uint(KVs[(kk + tg + 4) * LSTR + n]);
                mma_tf32(o[nt], a, b);
            }
        }
    }

    float inv0 = 1.f / l0, inv1 = 1.f / l1;
#pragma unroll
    for (int nt = 0; nt < 8; nt++) {
        int colg = h * HD + wn * 64 + nt * 8 + 2 * tg;
        size_t r0 = (size_t)(qt * 64 + row0) * QDIM + colg;
        size_t r1 = (size_t)(qt * 64 + row1) * QDIM + colg;
        *(float2*)&O[r0] = make_float2(__uint_as_float(f2tf(o[nt][0] * inv0)),
                                       __uint_as_float(f2tf(o[nt][1] * inv0)));
        *(float2*)&O[r1] = make_float2(__uint_as_float(f2tf(o[nt][2] * inv1)),
                                       __uint_as_float(f2tf(o[nt][3] * inv1)));
    }
}

// ---------------------------------------------------------------------------
// Launch
// ---------------------------------------------------------------------------
extern "C" void kernel_launch(void* const* d_in, const int* in_sizes, int n_in,
                              void* d_out, int out_size)
{
    const int*   positions = (const int*)d_in[0];
    const float* hidden    = (const float*)d_in[1];
    const float* wq        = (const float*)d_in[2];
    const float* wk        = (const float*)d_in[3];
    const float* wv        = (const float*)d_in[4];
    const float* wo        = (const float*)d_in[5];
    const float* qnw       = (const float*)d_in[6];
    const float* knw       = (const float*)d_in[7];
    float* out = (float*)d_out;

    float *q, *k, *v, *attn, *hid, *wqR, *wkR, *wvR, *woR;
    cudaGetSymbolAddress((void**)&q, g_q);
    cudaGetSymbolAddress((void**)&k, g_k);
    cudaGetSymbolAddress((void**)&v, g_v);
    cudaGetSymbolAddress((void**)&attn, g_attn);
    cudaGetSymbolAddress((void**)&hid, g_hid);
    cudaGetSymbolAddress((void**)&wqR, g_wqR);
    cudaGetSymbolAddress((void**)&wkR, g_wkR);
    cudaGetSymbolAddress((void**)&wvR, g_wvR);
    cudaGetSymbolAddress((void**)&woR, g_woR);

    // Prep: round all GEMM inputs to tf32 once
    {
        int n;
        n = HIDDEN * QDIM / 4;  round_tf32<<<(n + 255) / 256, 256>>>(wq, wqR, n);
        n = HIDDEN * KVDIM / 4; round_tf32<<<(n + 255) / 256, 256>>>(wk, wkR, n);
        n = HIDDEN * KVDIM / 4; round_tf32<<<(n + 255) / 256, 256>>>(wv, wvR, n);
        n = QDIM * HIDDEN / 4;  round_tf32<<<(n + 255) / 256, 256>>>(wo, woR, n);
        n = TT * HIDDEN / 4;    round_tf32<<<(n + 255) / 256, 256>>>(hidden, hid, n);
    }

    // QKV projections
    {
        int smem = GSMEM_FLOATS * (int)sizeof(float);   // 71680
        cudaFuncSetAttribute(tf32_gemm, cudaFuncAttributeMaxDynamicSharedMemorySize, smem);
        dim3 gq(QDIM / 128, TT / 128);
        tf32_gemm<<<gq, 128, smem>>>(hid, wqR, q, TT, QDIM, HIDDEN);
        dim3 gk(KVDIM / 128, TT / 128);
        tf32_gemm<<<gk, 128, smem>>>(hid, wkR, k, TT, KVDIM, HIDDEN);
        tf32_gemm<<<gk, 128, smem>>>(hid, wvR, v, TT, KVDIM, HIDDEN);
    }

    // RMSNorm + RoPE (emits tf32-rounded q/k); round v for flash
    {
        int rows = TT * NH + TT * NKV;
        int blocks = (rows + 3) / 4;
        norm_rope_kernel<<<blocks, 128>>>(q, k, positions, qnw, knw);
        int n = TT * KVDIM / 4;
        round_tf32<<<(n + 255) / 256, 256>>>(v, v, n);
    }

    // Flash attention
    {
        int smem = (2 * 64 * LSTR + 64 * PSTR + 256) * (int)sizeof(float);
        cudaFuncSetAttribute(flash_tf32,
                             cudaFuncAttributeMaxDynamicSharedMemorySize, smem);
        dim3 g(TT / 64, NH);
        flash_tf32<<<g, 256, smem>>>(q, k, v, attn);
    }

    // Output projection
    {
        int smem = GSMEM_FLOATS * (int)sizeof(float);
        dim3 go(HIDDEN / 128, TT / 128);
        tf32_gemm<<<go, 128, smem>>>(attn, woR, out, TT, HIDDEN, HIDDEN);
    }
}